// round 2
// baseline (speedup 1.0000x reference)
#include <cuda_runtime.h>

#define BATCH 16384
#define CTX   10
#define MAXC  24
#define EMBED 128
#define WARPS_PER_BLOCK 8
#define THREADS (WARPS_PER_BLOCK * 32)

__global__ void zero_out_kernel(float* out) {
    if (threadIdx.x == 0) out[0] = 0.0f;
}

__global__ __launch_bounds__(THREADS)
void cbow_hs_kernel(const int* __restrict__ context_words,
                    const int* __restrict__ paths,
                    const int* __restrict__ codes,
                    const int* __restrict__ mask,     // int32 0/1 (bool stored as i32)
                    const float* __restrict__ W_in,
                    const float* __restrict__ W_internal,
                    float* __restrict__ out)
{
    const int warp_id  = threadIdx.x >> 5;
    const int lane     = threadIdx.x & 31;
    const int row      = blockIdx.x * WARPS_PER_BLOCK + warp_id;

    __shared__ float warp_loss[WARPS_PER_BLOCK];

    float loss = 0.0f;

    if (row < BATCH) {
        // ---- Context vector: mean of 10 gathered embeddings.
        // Each lane owns 4 contiguous dims (float4) -> warp covers 128 dims,
        // each gather is a fully coalesced 512B row read.
        const int* cw = context_words + row * CTX;
        float4 v = make_float4(0.f, 0.f, 0.f, 0.f);
        #pragma unroll
        for (int i = 0; i < CTX; i++) {
            const int w = cw[i];   // warp-uniform broadcast load
            const float4 e = __ldg(reinterpret_cast<const float4*>(
                                       W_in + (long)w * EMBED) + lane);
            v.x += e.x; v.y += e.y; v.z += e.z; v.w += e.w;
        }
        const float inv_ctx = 1.0f / (float)CTX;
        v.x *= inv_ctx; v.y *= inv_ctx; v.z *= inv_ctx; v.w *= inv_ctx;

        // ---- Hierarchical softmax path walk (mask-gated: skip the embedding
        // load entirely when masked; branch is warp-uniform since mask is
        // per-(row,step), identical across lanes).
        const int* p = paths + row * MAXC;
        const int* c = codes + row * MAXC;
        const int* m = mask  + row * MAXC;

        #pragma unroll 4
        for (int l = 0; l < MAXC; l++) {
            if (m[l] == 0) continue;
            const int node = p[l];
            const float4 e = __ldg(reinterpret_cast<const float4*>(
                                       W_internal + (long)node * EMBED) + lane);
            float s = v.x * e.x + v.y * e.y + v.z * e.z + v.w * e.w;
            // warp-reduce the 128-dim dot product
            s += __shfl_xor_sync(0xffffffffu, s, 16);
            s += __shfl_xor_sync(0xffffffffu, s, 8);
            s += __shfl_xor_sync(0xffffffffu, s, 4);
            s += __shfl_xor_sync(0xffffffffu, s, 2);
            s += __shfl_xor_sync(0xffffffffu, s, 1);

            const float sign = (float)(2 * c[l] - 1);
            // -logsigmoid(sign*s) = softplus(-sign*s), numerically stable form
            const float z  = -sign * s;
            const float sp = fmaxf(z, 0.0f) + log1pf(expf(-fabsf(z)));
            loss += sp;
        }
    }

    // ---- Block reduction: all lanes hold identical `loss`; lane 0 publishes.
    if (lane == 0) warp_loss[warp_id] = loss;
    __syncthreads();

    if (warp_id == 0) {
        float s = (lane < WARPS_PER_BLOCK) ? warp_loss[lane] : 0.0f;
        s += __shfl_xor_sync(0xffffffffu, s, 4);
        s += __shfl_xor_sync(0xffffffffu, s, 2);
        s += __shfl_xor_sync(0xffffffffu, s, 1);
        if (lane == 0) atomicAdd(out, s * (1.0f / (float)BATCH));
    }
}

extern "C" void kernel_launch(void* const* d_in, const int* in_sizes, int n_in,
                              void* d_out, int out_size)
{
    const int*   context_words = (const int*)d_in[0];
    const int*   paths         = (const int*)d_in[1];
    const int*   codes         = (const int*)d_in[2];
    const int*   mask          = (const int*)d_in[3];
    const float* W_in          = (const float*)d_in[4];
    const float* W_internal    = (const float*)d_in[5];
    float*       out           = (float*)d_out;

    zero_out_kernel<<<1, 32>>>(out);

    const int grid = (BATCH + WARPS_PER_BLOCK - 1) / WARPS_PER_BLOCK;  // 2048
    cbow_hs_kernel<<<grid, THREADS>>>(context_words, paths, codes, mask,
                                      W_in, W_internal, out);
}

// round 3
// speedup vs baseline: 1.1317x; 1.1317x over previous
#include <cuda_runtime.h>

#define BATCH 16384
#define CTX   10
#define MAXC  24
#define EMBED 128
#define WPB   8
#define THREADS (WPB * 32)
#define PITCH 33   // 33-float row pitch -> bank (j*33+i)%32 = (j+i)%32, conflict-free

__global__ void zero_out_kernel(float* out) {
    if (threadIdx.x == 0) out[0] = 0.0f;
}

// Predicated vector gather: issues @p LDG.E.128, no branch, e stays 0 when pred==0.
__device__ __forceinline__ float4 pred_ldg128(const float4* addr, int pred) {
    float4 e = make_float4(0.f, 0.f, 0.f, 0.f);
    asm("{\n\t"
        ".reg .pred p;\n\t"
        "setp.ne.s32 p, %4, 0;\n\t"
        "@p ld.global.nc.v4.f32 {%0,%1,%2,%3}, [%5];\n\t"
        "}"
        : "+f"(e.x), "+f"(e.y), "+f"(e.z), "+f"(e.w)
        : "r"(pred), "l"(addr));
    return e;
}

__global__ __launch_bounds__(THREADS)
void cbow_hs_kernel(const int* __restrict__ context_words,
                    const int* __restrict__ paths,
                    const int* __restrict__ codes,
                    const int* __restrict__ mask,     // int32 0/1
                    const float* __restrict__ W_in,
                    const float* __restrict__ W_internal,
                    float* __restrict__ out)
{
    const int warp_id = threadIdx.x >> 5;
    const int lane    = threadIdx.x & 31;
    const int row     = blockIdx.x * WPB + warp_id;

    __shared__ float wsum[WPB * MAXC * PITCH];   // per-warp 24x33 transpose buffers
    __shared__ float warp_loss[WPB];

    float contrib = 0.0f;

    if (row < BATCH) {
        // ---- Phase 1: context vector (mean of 10 gathered rows).
        // Lane owns 4 contiguous dims; each gather = coalesced 512B row read.
        const int* cw = context_words + row * CTX;
        float4 v = make_float4(0.f, 0.f, 0.f, 0.f);
        #pragma unroll
        for (int i = 0; i < CTX; i++) {
            const int w = cw[i];
            const float4 e = __ldg(reinterpret_cast<const float4*>(
                                       W_in + (long)w * EMBED) + lane);
            v.x += e.x; v.y += e.y; v.z += e.z; v.w += e.w;
        }
        const float inv_ctx = 1.0f / (float)CTX;
        v.x *= inv_ctx; v.y *= inv_ctx; v.z *= inv_ctx; v.w *= inv_ctx;

        // ---- Phase 2: 24 predicated gathers + per-lane partial dots.
        // Two batches of 12 to bound register pressure; within a batch all
        // loads are independent -> high MLP, zero branches.
        float part[MAXC];
        #pragma unroll
        for (int h = 0; h < 2; h++) {
            const int4* p4 = reinterpret_cast<const int4*>(paths + row * MAXC + h * 12);
            const int4* m4 = reinterpret_cast<const int4*>(mask  + row * MAXC + h * 12);
            int4 P[3], M[3];
            #pragma unroll
            for (int q = 0; q < 3; q++) { P[q] = __ldg(p4 + q); M[q] = __ldg(m4 + q); }

            #pragma unroll
            for (int k = 0; k < 12; k++) {
                const int node = (k % 4 == 0) ? ((const int*)&P[k / 4])[0] :
                                 (k % 4 == 1) ? ((const int*)&P[k / 4])[1] :
                                 (k % 4 == 2) ? ((const int*)&P[k / 4])[2] :
                                                ((const int*)&P[k / 4])[3];
                const int mk   = (k % 4 == 0) ? ((const int*)&M[k / 4])[0] :
                                 (k % 4 == 1) ? ((const int*)&M[k / 4])[1] :
                                 (k % 4 == 2) ? ((const int*)&M[k / 4])[2] :
                                                ((const int*)&M[k / 4])[3];
                const float4 e = pred_ldg128(reinterpret_cast<const float4*>(
                                                 W_internal + (long)node * EMBED) + lane,
                                             mk);
                part[h * 12 + k] = fmaf(v.x, e.x,
                                   fmaf(v.y, e.y,
                                   fmaf(v.z, e.z, v.w * e.w)));
            }
        }

        // ---- Phase 3: warp transpose via smem, then lane j owns step j.
        float* ws = wsum + warp_id * (MAXC * PITCH);
        #pragma unroll
        for (int l = 0; l < MAXC; l++)
            ws[l * PITCH + lane] = part[l];
        __syncwarp();

        if (lane < MAXC) {
            const float* rp = ws + lane * PITCH;
            float s = 0.0f;
            #pragma unroll
            for (int i = 0; i < 32; i++) s += rp[i];   // conflict-free, pure ILP

            const int cj = codes[row * MAXC + lane];
            const int mj = mask [row * MAXC + lane];
            const float sign = (float)(2 * cj - 1);
            const float x = -sign * s;
            // softplus(x) = max(x,0) + log(1 + exp(-|x|)), fast MUFU version
            const float sp = fmaxf(x, 0.0f) + __logf(1.0f + __expf(-fabsf(x)));
            contrib = mj ? sp : 0.0f;
        }
    }

    // ---- Reduce 24 per-step losses across the warp, then across the block.
    contrib += __shfl_xor_sync(0xffffffffu, contrib, 16);
    contrib += __shfl_xor_sync(0xffffffffu, contrib, 8);
    contrib += __shfl_xor_sync(0xffffffffu, contrib, 4);
    contrib += __shfl_xor_sync(0xffffffffu, contrib, 2);
    contrib += __shfl_xor_sync(0xffffffffu, contrib, 1);

    if (lane == 0) warp_loss[warp_id] = contrib;
    __syncthreads();

    if (warp_id == 0) {
        float s = (lane < WPB) ? warp_loss[lane] : 0.0f;
        s += __shfl_xor_sync(0xffffffffu, s, 4);
        s += __shfl_xor_sync(0xffffffffu, s, 2);
        s += __shfl_xor_sync(0xffffffffu, s, 1);
        if (lane == 0) atomicAdd(out, s * (1.0f / (float)BATCH));
    }
}

extern "C" void kernel_launch(void* const* d_in, const int* in_sizes, int n_in,
                              void* d_out, int out_size)
{
    const int*   context_words = (const int*)d_in[0];
    const int*   paths         = (const int*)d_in[1];
    const int*   codes         = (const int*)d_in[2];
    const int*   mask          = (const int*)d_in[3];
    const float* W_in          = (const float*)d_in[4];
    const float* W_internal    = (const float*)d_in[5];
    float*       out           = (float*)d_out;

    zero_out_kernel<<<1, 32>>>(out);

    const int grid = (BATCH + WPB - 1) / WPB;   // 2048
    cbow_hs_kernel<<<grid, THREADS>>>(context_words, paths, codes, mask,
                                      W_in, W_internal, out);
}

// round 4
// speedup vs baseline: 1.3265x; 1.1722x over previous
#include <cuda_runtime.h>

#define BATCH 16384
#define CTX   10
#define MAXC  24
#define EMBED 128
#define WPB   8
#define THREADS (WPB * 32)
#define PITCH 36   // 36 words/row: STS banks (4l+i)%32 distinct per warp; rows 144B -> 16B aligned for LDS.128

__global__ void zero_out_kernel(float* out) {
    if (threadIdx.x == 0) out[0] = 0.0f;
}

// Predicated vector gather: @p LDG.E.128, no branch; e stays 0 when pred==0.
__device__ __forceinline__ float4 pred_ldg128(const float4* addr, int pred) {
    float4 e = make_float4(0.f, 0.f, 0.f, 0.f);
    asm("{\n\t"
        ".reg .pred p;\n\t"
        "setp.ne.s32 p, %4, 0;\n\t"
        "@p ld.global.nc.v4.f32 {%0,%1,%2,%3}, [%5];\n\t"
        "}"
        : "+f"(e.x), "+f"(e.y), "+f"(e.z), "+f"(e.w)
        : "r"(pred), "l"(addr));
    return e;
}

__global__ __launch_bounds__(THREADS, 6)   // cap regs ~42 -> 6 blocks/SM -> 75% occ ceiling
void cbow_hs_kernel(const int* __restrict__ context_words,
                    const int* __restrict__ paths,
                    const int* __restrict__ codes,
                    const int* __restrict__ mask,     // int32 0/1
                    const float* __restrict__ W_in,
                    const float* __restrict__ W_internal,
                    float* __restrict__ out)
{
    const int warp_id = threadIdx.x >> 5;
    const int lane    = threadIdx.x & 31;
    const int row     = blockIdx.x * WPB + warp_id;

    __shared__ float wsum[WPB][MAXC * PITCH];   // 8 * 24*36*4 = 27.6 KB
    __shared__ float warp_loss[WPB];

    float contrib = 0.0f;

    if (row < BATCH) {
        // ---- Phase 1: context vector (mean of 10 gathered 512B rows).
        const int* cw = context_words + row * CTX;
        float4 v = make_float4(0.f, 0.f, 0.f, 0.f);
        #pragma unroll
        for (int i = 0; i < CTX; i++) {
            const int w = cw[i];
            const float4 e = __ldg(reinterpret_cast<const float4*>(
                                       W_in + (long)w * EMBED) + lane);
            v.x += e.x; v.y += e.y; v.z += e.z; v.w += e.w;
        }
        const float inv_ctx = 1.0f / (float)CTX;
        v.x *= inv_ctx; v.y *= inv_ctx; v.z *= inv_ctx; v.w *= inv_ctx;

        // ---- Phase 2: 24 predicated gathers in 3 batches of 8; partial dot
        // is stored to smem immediately (no 24-float register array).
        float* ws = wsum[warp_id];
        const int4* p4 = reinterpret_cast<const int4*>(paths + row * MAXC);
        const int4* m4 = reinterpret_cast<const int4*>(mask  + row * MAXC);

        #pragma unroll
        for (int h = 0; h < 3; h++) {
            const int4 P0 = __ldg(p4 + h * 2), P1 = __ldg(p4 + h * 2 + 1);
            const int4 M0 = __ldg(m4 + h * 2), M1 = __ldg(m4 + h * 2 + 1);
            const int nodes[8] = {P0.x, P0.y, P0.z, P0.w, P1.x, P1.y, P1.z, P1.w};
            const int mks[8]   = {M0.x, M0.y, M0.z, M0.w, M1.x, M1.y, M1.z, M1.w};

            float4 E[8];
            #pragma unroll
            for (int k = 0; k < 8; k++)
                E[k] = pred_ldg128(reinterpret_cast<const float4*>(
                                       W_internal + (long)nodes[k] * EMBED) + lane,
                                   mks[k]);
            #pragma unroll
            for (int k = 0; k < 8; k++) {
                const float pt = fmaf(v.x, E[k].x,
                                 fmaf(v.y, E[k].y,
                                 fmaf(v.z, E[k].z, v.w * E[k].w)));
                ws[(h * 8 + k) * PITCH + lane] = pt;   // conflict-free STS
            }
        }
        __syncwarp();

        // ---- Phase 3: lane j (<24) sums step j's 32 partials via 8x LDS.128.
        if (lane < MAXC) {
            const float4* rp = reinterpret_cast<const float4*>(ws + lane * PITCH);
            float4 a0 = rp[0], a1 = rp[1], a2 = rp[2], a3 = rp[3];
            const float4 b0 = rp[4], b1 = rp[5], b2 = rp[6], b3 = rp[7];
            a0.x += b0.x; a0.y += b0.y; a0.z += b0.z; a0.w += b0.w;
            a1.x += b1.x; a1.y += b1.y; a1.z += b1.z; a1.w += b1.w;
            a2.x += b2.x; a2.y += b2.y; a2.z += b2.z; a2.w += b2.w;
            a3.x += b3.x; a3.y += b3.y; a3.z += b3.z; a3.w += b3.w;
            float s = ((a0.x + a0.y) + (a0.z + a0.w))
                    + ((a1.x + a1.y) + (a1.z + a1.w))
                    + ((a2.x + a2.y) + (a2.z + a2.w))
                    + ((a3.x + a3.y) + (a3.z + a3.w));

            const int cj = codes[row * MAXC + lane];
            const int mj = mask [row * MAXC + lane];
            const float sign = (float)(2 * cj - 1);
            const float x = -sign * s;
            // softplus(x) = max(x,0) + log(1 + exp(-|x|)), MUFU fast path
            const float sp = fmaxf(x, 0.0f) + __logf(1.0f + __expf(-fabsf(x)));
            contrib = mj ? sp : 0.0f;
        }
    }

    // ---- Reduce 24 step losses across the warp, then across the block.
    contrib += __shfl_xor_sync(0xffffffffu, contrib, 16);
    contrib += __shfl_xor_sync(0xffffffffu, contrib, 8);
    contrib += __shfl_xor_sync(0xffffffffu, contrib, 4);
    contrib += __shfl_xor_sync(0xffffffffu, contrib, 2);
    contrib += __shfl_xor_sync(0xffffffffu, contrib, 1);

    if (lane == 0) warp_loss[warp_id] = contrib;
    __syncthreads();

    if (warp_id == 0) {
        float s = (lane < WPB) ? warp_loss[lane] : 0.0f;
        s += __shfl_xor_sync(0xffffffffu, s, 4);
        s += __shfl_xor_sync(0xffffffffu, s, 2);
        s += __shfl_xor_sync(0xffffffffu, s, 1);
        if (lane == 0) atomicAdd(out, s * (1.0f / (float)BATCH));
    }
}

extern "C" void kernel_launch(void* const* d_in, const int* in_sizes, int n_in,
                              void* d_out, int out_size)
{
    const int*   context_words = (const int*)d_in[0];
    const int*   paths         = (const int*)d_in[1];
    const int*   codes         = (const int*)d_in[2];
    const int*   mask          = (const int*)d_in[3];
    const float* W_in          = (const float*)d_in[4];
    const float* W_internal    = (const float*)d_in[5];
    float*       out           = (float*)d_out;

    zero_out_kernel<<<1, 32>>>(out);

    const int grid = (BATCH + WPB - 1) / WPB;   // 2048
    cbow_hs_kernel<<<grid, THREADS>>>(context_words, paths, codes, mask,
                                      W_in, W_internal, out);
}